// round 2
// baseline (speedup 1.0000x reference)
#include <cuda_runtime.h>

// Problem constants (fixed shapes for GAT_88639535055056)
#define NN 50000          // nodes
#define NE 800000         // edges
#define NF 512            // input features
#define NH 8              // heads
#define OPH 32            // out per head
#define HO 256            // NH*OPH
#define ALPHA 0.2f

// ---------------- scratch (static device globals; no allocation) -------------
__device__ float g_Wh[(size_t)NN * HO];        // 51.2 MB: h@W + Wb
__device__ float g_es[NN * NH];                // e_s per node/head
__device__ float g_ed[NN * NH];                // e_d per node/head
__device__ int   g_cnt[NN];                    // in-degree histogram
__device__ int   g_rowptr[NN + 1];             // CSR row pointers (by dst)
__device__ int   g_cursor[NN];                 // scatter cursors
__device__ int   g_csrc[NE];                   // CSR: src node per slot
__device__ float g_csre[(size_t)NE * NH];      // CSR: leaky-relu'd e per slot/head

// ---------------- GEMM: Wh[m][j] = sum_k h[m][k] * W[j>>5][k][j&31] + Wb[j] --
#define BM 128
#define BN 64
#define BK 16
#define TM 8
#define TN 4

__global__ __launch_bounds__(256) void gemm_kernel(
    const float* __restrict__ h, const float* __restrict__ W,
    const float* __restrict__ Wb)
{
    __shared__ float As[BK][BM];
    __shared__ float Bs[BK][BN];

    const int t  = threadIdx.x;            // 0..255
    const int m0 = blockIdx.x * BM;
    const int j0 = blockIdx.y * BN;
    const int tx = t & 15;                 // 16 col groups of TN=4
    const int ty = t >> 4;                 // 16 row groups of TM=8

    float acc[TM][TN];
#pragma unroll
    for (int i = 0; i < TM; i++)
#pragma unroll
        for (int j = 0; j < TN; j++) acc[i][j] = 0.0f;

    const int a_row = t >> 2;              // 0..63
    const int a_col = (t & 3) * 4;         // 0,4,8,12
    const int b_row = t >> 4;              // k 0..15
    const int b_col = (t & 15) * 4;        // j_local 0..60

    for (int k0 = 0; k0 < NF; k0 += BK) {
        // load A tile (transposed into As[k][m]), rows a_row and a_row+64
#pragma unroll
        for (int r = 0; r < 2; r++) {
            int ml = a_row + r * 64;
            int m  = m0 + ml;
            float4 v = make_float4(0.f, 0.f, 0.f, 0.f);
            if (m < NN)
                v = *(const float4*)&h[(size_t)m * NF + k0 + a_col];
            As[a_col + 0][ml] = v.x;
            As[a_col + 1][ml] = v.y;
            As[a_col + 2][ml] = v.z;
            As[a_col + 3][ml] = v.w;
        }
        // load B tile: B[k][j] = W[head][k][o]; o in {0..28}, float4 stays
        // inside one head's 32-wide o range.
        {
            int j    = j0 + b_col;
            int head = j >> 5;
            int o    = j & 31;
            float4 v = *(const float4*)&W[((size_t)head * NF + (k0 + b_row)) * OPH + o];
            *(float4*)&Bs[b_row][b_col] = v;
        }
        __syncthreads();

#pragma unroll
        for (int kk = 0; kk < BK; kk++) {
            float a_f[TM], b_f[TN];
#pragma unroll
            for (int i = 0; i < TM; i++) a_f[i] = As[kk][ty * TM + i];
#pragma unroll
            for (int j = 0; j < TN; j++) b_f[j] = Bs[kk][tx * TN + j];
#pragma unroll
            for (int i = 0; i < TM; i++)
#pragma unroll
                for (int j = 0; j < TN; j++)
                    acc[i][j] = fmaf(a_f[i], b_f[j], acc[i][j]);
        }
        __syncthreads();
    }

    // epilogue: add bias, store
    const int nbase = j0 + tx * TN;
    float wbv[TN];
#pragma unroll
    for (int j = 0; j < TN; j++) wbv[j] = Wb[nbase + j];

#pragma unroll
    for (int i = 0; i < TM; i++) {
        int m = m0 + ty * TM + i;
        if (m < NN) {
            float4 o;
            o.x = acc[i][0] + wbv[0];
            o.y = acc[i][1] + wbv[1];
            o.z = acc[i][2] + wbv[2];
            o.w = acc[i][3] + wbv[3];
            *(float4*)&g_Wh[(size_t)m * HO + nbase] = o;
        }
    }
}

// ---------------- e_s / e_d: per-node per-head dot products ------------------
__global__ __launch_bounds__(256) void esd_kernel(const float* __restrict__ a)
{
    int gw   = (blockIdx.x * blockDim.x + threadIdx.x) >> 5;
    int lane = threadIdx.x & 31;
    if (gw >= NN) return;
    const float* whrow = &g_Wh[(size_t)gw * HO];
#pragma unroll
    for (int hh = 0; hh < NH; hh++) {
        float v  = whrow[hh * OPH + lane];
        float ps = v * a[hh * 64 + lane];        // a_src
        float pd = v * a[hh * 64 + 32 + lane];   // a_dst
#pragma unroll
        for (int off = 16; off; off >>= 1) {
            ps += __shfl_xor_sync(0xffffffffu, ps, off);
            pd += __shfl_xor_sync(0xffffffffu, pd, off);
        }
        if (lane == 0) {
            g_es[gw * NH + hh] = ps;
            g_ed[gw * NH + hh] = pd;
        }
    }
}

// ---------------- CSR build --------------------------------------------------
__global__ void zero_kernel()
{
    int i = blockIdx.x * blockDim.x + threadIdx.x;
    if (i < NN) g_cnt[i] = 0;
}

__global__ void hist_kernel(const int* __restrict__ dst)
{
    int i = blockIdx.x * blockDim.x + threadIdx.x;
    if (i < NE) atomicAdd(&g_cnt[dst[i]], 1);
}

__global__ __launch_bounds__(1024) void scan_kernel()
{
    __shared__ int sh[1024];
    __shared__ int carry_s;
    int t = threadIdx.x;
    if (t == 0) carry_s = 0;
    __syncthreads();
    for (int base = 0; base < NN; base += 1024) {
        int idx = base + t;
        int v   = (idx < NN) ? g_cnt[idx] : 0;
        sh[t] = v;
        __syncthreads();
#pragma unroll
        for (int off = 1; off < 1024; off <<= 1) {
            int x = (t >= off) ? sh[t - off] : 0;
            __syncthreads();
            sh[t] += x;
            __syncthreads();
        }
        int excl = sh[t] - v + carry_s;
        if (idx < NN) {
            g_rowptr[idx] = excl;
            g_cursor[idx] = excl;
        }
        __syncthreads();
        if (t == 1023) carry_s += sh[1023];
        __syncthreads();
    }
    if (t == 0) g_rowptr[NN] = carry_s;
}

// scatter edges into CSR slots; precompute leaky-relu'd e per head
__global__ __launch_bounds__(256) void scatter_kernel(
    const int* __restrict__ src, const int* __restrict__ dst,
    const float* __restrict__ ab)
{
    int i = blockIdx.x * blockDim.x + threadIdx.x;
    if (i >= NE) return;
    int s   = src[i];
    int d   = dst[i];
    int pos = atomicAdd(&g_cursor[d], 1);
    g_csrc[pos] = s;

    const float4* es = (const float4*)&g_es[s * NH];
    const float4* ed = (const float4*)&g_ed[d * NH];
    float4 sa = es[0], sb = es[1];
    float4 da = ed[0], db = ed[1];

    float e[NH];
    e[0] = sa.x + da.x + ab[0];
    e[1] = sa.y + da.y + ab[1];
    e[2] = sa.z + da.z + ab[2];
    e[3] = sa.w + da.w + ab[3];
    e[4] = sb.x + db.x + ab[4];
    e[5] = sb.y + db.y + ab[5];
    e[6] = sb.z + db.z + ab[6];
    e[7] = sb.w + db.w + ab[7];
#pragma unroll
    for (int hh = 0; hh < NH; hh++) e[hh] = e[hh] > 0.f ? e[hh] : ALPHA * e[hh];

    float4* o = (float4*)&g_csre[(size_t)pos * NH];
    o[0] = make_float4(e[0], e[1], e[2], e[3]);
    o[1] = make_float4(e[4], e[5], e[6], e[7]);
}

// ---------------- per-node softmax + aggregation (warp per node) -------------
__global__ __launch_bounds__(256) void agg_kernel(float* __restrict__ out)
{
    int gw   = (blockIdx.x * blockDim.x + threadIdx.x) >> 5;
    int lane = threadIdx.x & 31;
    if (gw >= NN) return;

    int start = g_rowptr[gw];
    int end   = g_rowptr[gw + 1];

    if (start == end) {
#pragma unroll
        for (int hh = 0; hh < NH; hh++)
            out[(size_t)gw * HO + hh * OPH + lane] = 0.0f;
        return;
    }

    // pass 1: per-head max
    float m[NH];
#pragma unroll
    for (int hh = 0; hh < NH; hh++) m[hh] = -1e30f;
    for (int p = start + lane; p < end; p += 32) {
        const float4* ep = (const float4*)&g_csre[(size_t)p * NH];
        float4 ea = ep[0], eb = ep[1];
        m[0] = fmaxf(m[0], ea.x); m[1] = fmaxf(m[1], ea.y);
        m[2] = fmaxf(m[2], ea.z); m[3] = fmaxf(m[3], ea.w);
        m[4] = fmaxf(m[4], eb.x); m[5] = fmaxf(m[5], eb.y);
        m[6] = fmaxf(m[6], eb.z); m[7] = fmaxf(m[7], eb.w);
    }
#pragma unroll
    for (int hh = 0; hh < NH; hh++)
#pragma unroll
        for (int off = 16; off; off >>= 1)
            m[hh] = fmaxf(m[hh], __shfl_xor_sync(0xffffffffu, m[hh], off));

    // pass 2: per-head denominator
    float den[NH];
#pragma unroll
    for (int hh = 0; hh < NH; hh++) den[hh] = 0.0f;
    for (int p = start + lane; p < end; p += 32) {
        const float4* ep = (const float4*)&g_csre[(size_t)p * NH];
        float4 ea = ep[0], eb = ep[1];
        den[0] += __expf(ea.x - m[0]); den[1] += __expf(ea.y - m[1]);
        den[2] += __expf(ea.z - m[2]); den[3] += __expf(ea.w - m[3]);
        den[4] += __expf(eb.x - m[4]); den[5] += __expf(eb.y - m[5]);
        den[6] += __expf(eb.z - m[6]); den[7] += __expf(eb.w - m[7]);
    }
#pragma unroll
    for (int hh = 0; hh < NH; hh++)
#pragma unroll
        for (int off = 16; off; off >>= 1)
            den[hh] += __shfl_xor_sync(0xffffffffu, den[hh], off);

    // this lane's head (lane&7) for weight computation in pass 3
    float my_m = 0.f, my_inv = 0.f;
#pragma unroll
    for (int hh = 0; hh < NH; hh++)
        if ((lane & 7) == hh) { my_m = m[hh]; my_inv = 1.0f / den[hh]; }

    // pass 3: weighted aggregation, warp-serial over edges
    float acc[NH];
#pragma unroll
    for (int hh = 0; hh < NH; hh++) acc[hh] = 0.0f;

    for (int p = start; p < end; p++) {
        int   s = g_csrc[p];                          // broadcast load
        float e = g_csre[(size_t)p * NH + (lane & 7)];
        float w = __expf(e - my_m) * my_inv;          // att for head lane&7
        const float* whrow = &g_Wh[(size_t)s * HO];
#pragma unroll
        for (int hh = 0; hh < NH; hh++) {
            float att = __shfl_sync(0xffffffffu, w, hh); // lane hh owns head hh
            acc[hh] = fmaf(att, whrow[hh * OPH + lane], acc[hh]);
        }
    }

#pragma unroll
    for (int hh = 0; hh < NH; hh++)
        out[(size_t)gw * HO + hh * OPH + lane] = acc[hh];
}

// ---------------- launch -----------------------------------------------------
extern "C" void kernel_launch(void* const* d_in, const int* in_sizes, int n_in,
                              void* d_out, int out_size)
{
    const float* h   = (const float*)d_in[0];  // [NN, NF]
    const int*   src = (const int*)  d_in[1];  // [NE]
    const int*   dst = (const int*)  d_in[2];  // [NE]
    const float* W   = (const float*)d_in[3];  // [NH, NF, OPH]
    const float* Wb  = (const float*)d_in[4];  // [NH, OPH]
    const float* a   = (const float*)d_in[5];  // [NH, 2*OPH]
    const float* ab  = (const float*)d_in[6];  // [NH]
    float*       out = (float*)d_out;          // [NN, HO]

    (void)in_sizes; (void)n_in; (void)out_size;

    // CSR histogram can start immediately (independent of GEMM)
    zero_kernel<<<(NN + 255) / 256, 256>>>();
    hist_kernel<<<(NE + 255) / 256, 256>>>(dst);

    // Wh = h@W + Wb
    dim3 ggrid((NN + BM - 1) / BM, HO / BN);
    gemm_kernel<<<ggrid, 256>>>(h, W, Wb);

    // per-node attention logits
    esd_kernel<<<(NN * 32 + 255) / 256, 256>>>(a);

    // CSR finalize
    scan_kernel<<<1, 1024>>>();
    scatter_kernel<<<(NE + 255) / 256, 256>>>(src, dst, ab);

    // softmax + aggregate
    agg_kernel<<<(NN * 32 + 255) / 256, 256>>>(out);
}

// round 7
// speedup vs baseline: 1.5690x; 1.5690x over previous
#include <cuda_runtime.h>
#include <cuda_bf16.h>
#include <cstdint>
#include <cstddef>

// Problem constants (fixed shapes for GAT_88639535055056)
#define NN 50000          // nodes
#define NE 800000         // edges
#define NF 512            // input features
#define NH 8              // heads
#define OPH 32            // out per head
#define HO 256            // NH*OPH
#define ALPHA 0.2f

// GEMM tiling (mma.sync m16n8k16 bf16, split hi/lo for fp32-grade accuracy)
#define BM 128
#define BN 128            // per CTA; grid.y=2 covers N=256
#define BK 32
#define NCHUNK (NF / BK)  // 16
#define ASTR 40           // bf16 elems per smem row (stride 80 B, conflict-free)
#define TILEB (128 * ASTR * 2)   // 10240 B per tile

// ---------------- scratch (static device globals; no allocation) -------------
__device__ float g_Wh[(size_t)NN * HO];        // 51.2 MB: h@W + Wb
__device__ float g_es[NN * NH];                // e_s per node/head
__device__ float g_ed[NN * NH];                // e_d per node/head
__device__ int   g_cnt[NN];                    // in-degree histogram
__device__ int   g_rowptr[NN + 1];             // CSR row pointers (by dst)
__device__ int   g_cursor[NN];                 // scatter cursors
__device__ int   g_csrc[NE];                   // CSR: src node per slot
__device__ float g_csre[(size_t)NE * NH];      // CSR: leaky-relu'd e per slot/head

// ---------------- helpers ----------------------------------------------------
__device__ __forceinline__ uint32_t pack_bf2(float a, float b) {
    __nv_bfloat162 t = __floats2bfloat162_rn(a, b);
    return *(uint32_t*)&t;
}
__device__ __forceinline__ void mma16816(float* d, const uint32_t* a,
                                         const uint32_t* b) {
    asm volatile(
        "mma.sync.aligned.m16n8k16.row.col.f32.bf16.bf16.f32 "
        "{%0,%1,%2,%3}, {%4,%5,%6,%7}, {%8,%9}, {%0,%1,%2,%3};\n"
        : "+f"(d[0]), "+f"(d[1]), "+f"(d[2]), "+f"(d[3])
        : "r"(a[0]), "r"(a[1]), "r"(a[2]), "r"(a[3]), "r"(b[0]), "r"(b[1]));
}
__device__ __forceinline__ void store_hi_lo_A(char* Ah, char* Al, int m, int kq,
                                              float4 v) {
    float hx = __bfloat162float(__float2bfloat16(v.x));
    float hy = __bfloat162float(__float2bfloat16(v.y));
    float hz = __bfloat162float(__float2bfloat16(v.z));
    float hw = __bfloat162float(__float2bfloat16(v.w));
    int off = m * (ASTR * 2) + kq * 2;
    *(uint2*)(Ah + off) = make_uint2(pack_bf2(v.x, v.y), pack_bf2(v.z, v.w));
    *(uint2*)(Al + off) = make_uint2(pack_bf2(v.x - hx, v.y - hy),
                                     pack_bf2(v.z - hz, v.w - hw));
}
// B tile: smem [n][k], n local 0..127 (head-major), k contiguous pairs
__device__ __forceinline__ void load_B_chunk(char* Bh, char* Bl,
                                             const float* __restrict__ W,
                                             int by, int k0, int t) {
#pragma unroll
    for (int j = 0; j < 8; j++) {
        int i = t + j * 256;
        int n = i & 127;
        int k = (i >> 7) * 2;
        int head = by * 4 + (n >> 5);
        int o = n & 31;
        const float* p = &W[((size_t)head * NF + (k0 + k)) * OPH + o];
        float v0 = p[0], v1 = p[OPH];
        float h0 = __bfloat162float(__float2bfloat16(v0));
        float h1 = __bfloat162float(__float2bfloat16(v1));
        int off = n * (ASTR * 2) + k * 2;
        *(uint32_t*)(Bh + off) = pack_bf2(v0, v1);
        *(uint32_t*)(Bl + off) = pack_bf2(v0 - h0, v1 - h1);
    }
}

// ---------------- GEMM: mma.sync split-bf16, fused esd epilogue --------------
// Static shared memory (42.5 KB < 48 KB): no dynamic smem, no
// cudaFuncSetAttribute in the (graph-captured) launch path.
__global__ __launch_bounds__(256, 2) void gemm_kernel(
    const float* __restrict__ h, const float* __restrict__ W,
    const float* __restrict__ Wb, const float* __restrict__ avec)
{
    __shared__ __align__(16) char sAh[TILEB];
    __shared__ __align__(16) char sAl[TILEB];
    __shared__ __align__(16) char sBh[TILEB];
    __shared__ __align__(16) char sBl[TILEB];
    __shared__ float wb_s[128];
    __shared__ float av_s[256];

    const int t    = threadIdx.x;
    const int lane = t & 31;
    const int wid  = t >> 5;
    const int m0   = blockIdx.x * BM;
    const int by   = blockIdx.y;            // 0/1: heads 0-3 / 4-7
    const int wm0  = (wid & 3) * 32;        // warp row offset
    const int wn0  = (wid >> 2) * 64;       // warp col offset (2 heads)
    const int q    = lane >> 2;
    const int tq   = lane & 3;

    if (t < 128) wb_s[t] = Wb[by * 128 + t];
    if (t < 256) av_s[t] = avec[by * 256 + t];

    float acc[2][8][4];
#pragma unroll
    for (int mi = 0; mi < 2; mi++)
#pragma unroll
        for (int ni = 0; ni < 8; ni++)
#pragma unroll
            for (int r = 0; r < 4; r++) acc[mi][ni][r] = 0.0f;

    // prologue: chunk 0
    {
#pragma unroll
        for (int j = 0; j < 4; j++) {
            int i = t + j * 256;
            int m = i >> 3;
            int kq = (i & 7) * 4;
            float4 v = make_float4(0.f, 0.f, 0.f, 0.f);
            if (m0 + m < NN) v = *(const float4*)&h[(size_t)(m0 + m) * NF + kq];
            store_hi_lo_A(sAh, sAl, m, kq, v);
        }
        load_B_chunk(sBh, sBl, W, by, 0, t);
    }
    __syncthreads();

    for (int c = 0; c < NCHUNK; c++) {
        // prefetch next A chunk (DRAM) into regs during compute
        float4 apf[4];
        if (c + 1 < NCHUNK) {
            int k0n = (c + 1) * BK;
#pragma unroll
            for (int j = 0; j < 4; j++) {
                int i = t + j * 256;
                int m = i >> 3;
                int kq = (i & 7) * 4;
                apf[j] = make_float4(0.f, 0.f, 0.f, 0.f);
                if (m0 + m < NN)
                    apf[j] = *(const float4*)&h[(size_t)(m0 + m) * NF + k0n + kq];
            }
        }

        // compute chunk c
#pragma unroll
        for (int ks = 0; ks < 2; ks++) {
            const int kb = ks * 16 + tq * 2;          // this thread's k base
            uint32_t ah[2][4], al[2][4];
#pragma unroll
            for (int mi = 0; mi < 2; mi++) {
                int r = wm0 + mi * 16 + q;
                const char* ba = sAh + r * (ASTR * 2) + kb * 2;
                ah[mi][0] = *(const uint32_t*)(ba);
                ah[mi][1] = *(const uint32_t*)(ba + 8 * (ASTR * 2));
                ah[mi][2] = *(const uint32_t*)(ba + 16);
                ah[mi][3] = *(const uint32_t*)(ba + 8 * (ASTR * 2) + 16);
                const char* bl_ = sAl + r * (ASTR * 2) + kb * 2;
                al[mi][0] = *(const uint32_t*)(bl_);
                al[mi][1] = *(const uint32_t*)(bl_ + 8 * (ASTR * 2));
                al[mi][2] = *(const uint32_t*)(bl_ + 16);
                al[mi][3] = *(const uint32_t*)(bl_ + 8 * (ASTR * 2) + 16);
            }
#pragma unroll
            for (int ni = 0; ni < 8; ni++) {
                int n = wn0 + ni * 8 + q;
                const char* bb = sBh + n * (ASTR * 2) + kb * 2;
                uint32_t bh[2] = { *(const uint32_t*)bb,
                                   *(const uint32_t*)(bb + 16) };
                const char* bb2 = sBl + n * (ASTR * 2) + kb * 2;
                uint32_t bl2[2] = { *(const uint32_t*)bb2,
                                    *(const uint32_t*)(bb2 + 16) };
#pragma unroll
                for (int mi = 0; mi < 2; mi++) {
                    mma16816(acc[mi][ni], ah[mi], bh);
                    mma16816(acc[mi][ni], ah[mi], bl2);
                    mma16816(acc[mi][ni], al[mi], bh);
                }
            }
        }
        __syncthreads();   // all reads of chunk c done

        // stage chunk c+1 into the (single) buffer
        if (c + 1 < NCHUNK) {
#pragma unroll
            for (int j = 0; j < 4; j++) {
                int i = t + j * 256;
                store_hi_lo_A(sAh, sAl, i >> 3, (i & 7) * 4, apf[j]);
            }
            load_B_chunk(sBh, sBl, W, by, (c + 1) * BK, t);
            __syncthreads();
        }
    }

    // ---- epilogue: bias add, store Wh, fused e_s/e_d ----
#pragma unroll
    for (int mi = 0; mi < 2; mi++) {
        int r0 = m0 + wm0 + mi * 16 + q;
        int r1 = r0 + 8;
        float esA0 = 0.f, edA0 = 0.f, esA1 = 0.f, edA1 = 0.f;
        float esB0 = 0.f, edB0 = 0.f, esB1 = 0.f, edB1 = 0.f;
#pragma unroll
        for (int ni = 0; ni < 8; ni++) {
            int jl = wn0 + ni * 8 + tq * 2;           // local col 0..127
            float wb0 = wb_s[jl], wb1 = wb_s[jl + 1];
            float d0 = acc[mi][ni][0] + wb0;
            float d1 = acc[mi][ni][1] + wb1;
            float d2 = acc[mi][ni][2] + wb0;
            float d3 = acc[mi][ni][3] + wb1;
            int gc = by * 128 + jl;
            if (r0 < NN) *(float2*)&g_Wh[(size_t)r0 * HO + gc] = make_float2(d0, d1);
            if (r1 < NN) *(float2*)&g_Wh[(size_t)r1 * HO + gc] = make_float2(d2, d3);
            int hl = jl >> 5;
            int oo = jl & 31;
            float as0 = av_s[hl * 64 + oo],      as1 = av_s[hl * 64 + oo + 1];
            float ad0 = av_s[hl * 64 + 32 + oo], ad1 = av_s[hl * 64 + 32 + oo + 1];
            if (ni < 4) {
                esA0 += d0 * as0 + d1 * as1;  edA0 += d0 * ad0 + d1 * ad1;
                esA1 += d2 * as0 + d3 * as1;  edA1 += d2 * ad0 + d3 * ad1;
            } else {
                esB0 += d0 * as0 + d1 * as1;  edB0 += d0 * ad0 + d1 * ad1;
                esB1 += d2 * as0 + d3 * as1;  edB1 += d2 * ad0 + d3 * ad1;
            }
        }
        // reduce over the 4 lanes of the quad (tq dimension)
#pragma unroll
        for (int off = 1; off <= 2; off <<= 1) {
            esA0 += __shfl_xor_sync(0xffffffffu, esA0, off);
            edA0 += __shfl_xor_sync(0xffffffffu, edA0, off);
            esA1 += __shfl_xor_sync(0xffffffffu, esA1, off);
            edA1 += __shfl_xor_sync(0xffffffffu, edA1, off);
            esB0 += __shfl_xor_sync(0xffffffffu, esB0, off);
            edB0 += __shfl_xor_sync(0xffffffffu, edB0, off);
            esB1 += __shfl_xor_sync(0xffffffffu, esB1, off);
            edB1 += __shfl_xor_sync(0xffffffffu, edB1, off);
        }
        if (tq == 0) {
            int headA = by * 4 + (wn0 >> 5);
            int headB = headA + 1;
            if (r0 < NN) {
                g_es[r0 * NH + headA] = esA0;  g_ed[r0 * NH + headA] = edA0;
                g_es[r0 * NH + headB] = esB0;  g_ed[r0 * NH + headB] = edB0;
            }
            if (r1 < NN) {
                g_es[r1 * NH + headA] = esA1;  g_ed[r1 * NH + headA] = edA1;
                g_es[r1 * NH + headB] = esB1;  g_ed[r1 * NH + headB] = edB1;
            }
        }
    }
}

// ---------------- CSR build --------------------------------------------------
__global__ void zero_kernel()
{
    int i = blockIdx.x * blockDim.x + threadIdx.x;
    if (i < NN) g_cnt[i] = 0;
}

__global__ void hist_kernel(const int* __restrict__ dst)
{
    int i = blockIdx.x * blockDim.x + threadIdx.x;
    if (i < NE) atomicAdd(&g_cnt[dst[i]], 1);
}

__global__ __launch_bounds__(1024) void scan_kernel()
{
    __shared__ int sh[1024];
    __shared__ int carry_s;
    int t = threadIdx.x;
    if (t == 0) carry_s = 0;
    __syncthreads();
    for (int base = 0; base < NN; base += 1024) {
        int idx = base + t;
        int v   = (idx < NN) ? g_cnt[idx] : 0;
        sh[t] = v;
        __syncthreads();
#pragma unroll
        for (int off = 1; off < 1024; off <<= 1) {
            int x = (t >= off) ? sh[t - off] : 0;
            __syncthreads();
            sh[t] += x;
            __syncthreads();
        }
        int excl = sh[t] - v + carry_s;
        if (idx < NN) {
            g_rowptr[idx] = excl;
            g_cursor[idx] = excl;
        }
        __syncthreads();
        if (t == 1023) carry_s += sh[1023];
        __syncthreads();
    }
    if (t == 0) g_rowptr[NN] = carry_s;
}

// scatter edges into CSR slots; precompute leaky-relu'd e per head
__global__ __launch_bounds__(256) void scatter_kernel(
    const int* __restrict__ src, const int* __restrict__ dst,
    const float* __restrict__ ab)
{
    int i = blockIdx.x * blockDim.x + threadIdx.x;
    if (i >= NE) return;
    int s   = src[i];
    int d   = dst[i];
    int pos = atomicAdd(&g_cursor[d], 1);
    g_csrc[pos] = s;

    const float4* es = (const float4*)&g_es[s * NH];
    const float4* ed = (const float4*)&g_ed[d * NH];
    float4 sa = es[0], sb = es[1];
    float4 da = ed[0], db = ed[1];

    float e[NH];
    e[0] = sa.x + da.x + ab[0];
    e[1] = sa.y + da.y + ab[1];
    e[2] = sa.z + da.z + ab[2];
    e[3] = sa.w + da.w + ab[3];
    e[4] = sb.x + db.x + ab[4];
    e[5] = sb.y + db.y + ab[5];
    e[6] = sb.z + db.z + ab[6];
    e[7] = sb.w + db.w + ab[7];
#pragma unroll
    for (int hh = 0; hh < NH; hh++) e[hh] = e[hh] > 0.f ? e[hh] : ALPHA * e[hh];

    float4* o = (float4*)&g_csre[(size_t)pos * NH];
    o[0] = make_float4(e[0], e[1], e[2], e[3]);
    o[1] = make_float4(e[4], e[5], e[6], e[7]);
}

// ---------------- per-node softmax + aggregation (warp per node) -------------
__global__ __launch_bounds__(256) void agg_kernel(float* __restrict__ out)
{
    int gw   = (blockIdx.x * blockDim.x + threadIdx.x) >> 5;
    int lane = threadIdx.x & 31;
    if (gw >= NN) return;

    int start = g_rowptr[gw];
    int end   = g_rowptr[gw + 1];

    if (start == end) {
#pragma unroll
        for (int hh = 0; hh < NH; hh++)
            out[(size_t)gw * HO + hh * OPH + lane] = 0.0f;
        return;
    }

    // pass 1: per-head max
    float m[NH];
#pragma unroll
    for (int hh = 0; hh < NH; hh++) m[hh] = -1e30f;
    for (int p = start + lane; p < end; p += 32) {
        const float4* ep = (const float4*)&g_csre[(size_t)p * NH];
        float4 ea = ep[0], eb = ep[1];
        m[0] = fmaxf(m[0], ea.x); m[1] = fmaxf(m[1], ea.y);
        m[2] = fmaxf(m[2], ea.z); m[3] = fmaxf(m[3], ea.w);
        m[4] = fmaxf(m[4], eb.x); m[5] = fmaxf(m[5], eb.y);
        m[6] = fmaxf(m[6], eb.z); m[7] = fmaxf(m[7], eb.w);
    }
#pragma unroll
    for (int hh = 0; hh < NH; hh++)
#pragma unroll
        for (int off = 16; off; off >>= 1)
            m[hh] = fmaxf(m[hh], __shfl_xor_sync(0xffffffffu, m[hh], off));

    // pass 2: per-head denominator
    float den[NH];
#pragma unroll
    for (int hh = 0; hh < NH; hh++) den[hh] = 0.0f;
    for (int p = start + lane; p < end; p += 32) {
        const float4* ep = (const float4*)&g_csre[(size_t)p * NH];
        float4 ea = ep[0], eb = ep[1];
        den[0] += __expf(ea.x - m[0]); den[1] += __expf(ea.y - m[1]);
        den[2] += __expf(ea.z - m[2]); den[3] += __expf(ea.w - m[3]);
        den[4] += __expf(eb.x - m[4]); den[5] += __expf(eb.y - m[5]);
        den[6] += __expf(eb.z - m[6]); den[7] += __expf(eb.w - m[7]);
    }
#pragma unroll
    for (int hh = 0; hh < NH; hh++)
#pragma unroll
        for (int off = 16; off; off >>= 1)
            den[hh] += __shfl_xor_sync(0xffffffffu, den[hh], off);

    float my_m = 0.f, my_inv = 0.f;
#pragma unroll
    for (int hh = 0; hh < NH; hh++)
        if ((lane & 7) == hh) { my_m = m[hh]; my_inv = 1.0f / den[hh]; }

    // pass 3: weighted aggregation, warp-serial over edges
    float acc[NH];
#pragma unroll
    for (int hh = 0; hh < NH; hh++) acc[hh] = 0.0f;

    for (int p = start; p < end; p++) {
        int   s = g_csrc[p];                          // broadcast load
        float e = g_csre[(size_t)p * NH + (lane & 7)];
        float w = __expf(e - my_m) * my_inv;          // att for head lane&7
        const float* whrow = &g_Wh[(size_t)s * HO];
#pragma unroll
        for (int hh = 0; hh < NH; hh++) {
            float att = __shfl_sync(0xffffffffu, w, hh); // lane hh owns head hh
            acc[hh] = fmaf(att, whrow[hh * OPH + lane], acc[hh]);
        }
    }

#pragma unroll
    for (int hh = 0; hh < NH; hh++)
        out[(size_t)gw * HO + hh * OPH + lane] = acc[hh];
}

// ---------------- launch -----------------------------------------------------
extern "C" void kernel_launch(void* const* d_in, const int* in_sizes, int n_in,
                              void* d_out, int out_size)
{
    const float* h   = (const float*)d_in[0];  // [NN, NF]
    const int*   src = (const int*)  d_in[1];  // [NE]
    const int*   dst = (const int*)  d_in[2];  // [NE]
    const float* W   = (const float*)d_in[3];  // [NH, NF, OPH]
    const float* Wb  = (const float*)d_in[4];  // [NH, OPH]
    const float* a   = (const float*)d_in[5];  // [NH, 2*OPH]
    const float* ab  = (const float*)d_in[6];  // [NH]
    float*       out = (float*)d_out;          // [NN, HO]

    (void)in_sizes; (void)n_in; (void)out_size;

    // CSR histogram (independent of GEMM)
    zero_kernel<<<(NN + 255) / 256, 256>>>();
    hist_kernel<<<(NE + 255) / 256, 256>>>(dst);

    // Wh = h@W + Wb (mma.sync split-bf16) with fused e_s/e_d epilogue
    dim3 ggrid((NN + BM - 1) / BM, 2);
    gemm_kernel<<<ggrid, 256>>>(h, W, Wb, a);

    // CSR finalize
    scan_kernel<<<1, 1024>>>();
    scatter_kernel<<<(NE + 255) / 256, 256>>>(src, dst, ab);

    // softmax + aggregate
    agg_kernel<<<(NN * 32 + 255) / 256, 256>>>(out);
}